// round 3
// baseline (speedup 1.0000x reference)
#include <cuda_runtime.h>
#include <cuda_bf16.h>
#include <math.h>

#define BB 64
#define TT 512
#define EE 512
#define HH 1024
#define GG 4096   // 4*H
#define CC 4
#define NBLK 128  // persistent recurrence blocks; each owns 8 hidden units

// ---------------------------------------------------------------------------
// Global scratch (static device arrays — no runtime allocation)
// ---------------------------------------------------------------------------
__device__ float g_xp[(size_t)TT * BB * GG];          // [T][B][4H] input projections
__device__ float g_h[BB * HH];                        // final hidden state (t=511)
// h staged as bf16 hi/lo MMA A-fragments: [buf][ktile 64][mtile 4][hl 2][lane 32] x 16B
__device__ uint4 g_hstage[2][64 * 4 * 2 * 32];
__device__ unsigned g_bar;

// ---------------------------------------------------------------------------
// helpers
// ---------------------------------------------------------------------------
__device__ __forceinline__ void cpasync16(unsigned dst, const void* src) {
    asm volatile("cp.async.cg.shared.global [%0], [%1], 16;" :: "r"(dst), "l"(src));
}
__device__ __forceinline__ uint4 lds128(unsigned addr) {
    uint4 v;
    asm volatile("ld.shared.v4.u32 {%0,%1,%2,%3}, [%4];"
                 : "=r"(v.x), "=r"(v.y), "=r"(v.z), "=r"(v.w) : "r"(addr));
    return v;
}
__device__ __forceinline__ void mma16816(float* d, const uint4& a, unsigned b0, unsigned b1) {
    asm volatile("mma.sync.aligned.m16n8k16.row.col.f32.bf16.bf16.f32 "
                 "{%0,%1,%2,%3}, {%4,%5,%6,%7}, {%8,%9}, {%0,%1,%2,%3};"
                 : "+f"(d[0]), "+f"(d[1]), "+f"(d[2]), "+f"(d[3])
                 : "r"(a.x), "r"(a.y), "r"(a.z), "r"(a.w), "r"(b0), "r"(b1));
}

// ---------------------------------------------------------------------------
// init: zero barrier counter + h(-1) staging buffer 0
// ---------------------------------------------------------------------------
__global__ void init_kernel() {
    int i = blockIdx.x * blockDim.x + threadIdx.x;
    if (i == 0) g_bar = 0u;
    if (i < 64 * 4 * 2 * 32) g_hstage[0][i] = make_uint4(0u, 0u, 0u, 0u);
}

// ---------------------------------------------------------------------------
// xproj (validated round 0/1): XP[t*B+b][g] = emb[tokens[b][t]] . Wi[:,g] + b[g]
// ---------------------------------------------------------------------------
__global__ __launch_bounds__(256) void xproj_kernel(
        const int* __restrict__ tokens, const float* __restrict__ emb,
        const float* __restrict__ Wi, const float* __restrict__ bias) {
    __shared__ float As[8][128];
    __shared__ float Bs[8][128];
    const int m0 = blockIdx.x * 128;
    const int n0 = blockIdx.y * 128;
    const int tid = threadIdx.x;
    const int tx = tid & 15, ty = tid >> 4;
    const int tx4 = tx * 4, ty4 = ty * 4;

    const int arow = tid & 127;
    const int akq  = (tid >> 7) * 4;
    const int m  = m0 + arow;
    const int t_ = m >> 6;
    const int b_ = m & 63;
    const float* erow = emb + (size_t)tokens[b_ * TT + t_] * EE;

    const int bk = tid >> 5;
    const int bn = (tid & 31) * 4;

    float acc[8][8];
#pragma unroll
    for (int i = 0; i < 8; i++)
#pragma unroll
        for (int j = 0; j < 8; j++) acc[i][j] = 0.f;

    for (int e0 = 0; e0 < EE; e0 += 8) {
        float4 av = *(const float4*)(erow + e0 + akq);
        float4 wv = *(const float4*)(Wi + (size_t)(e0 + bk) * GG + n0 + bn);
        As[akq + 0][arow] = av.x;
        As[akq + 1][arow] = av.y;
        As[akq + 2][arow] = av.z;
        As[akq + 3][arow] = av.w;
        *(float4*)&Bs[bk][bn] = wv;
        __syncthreads();
#pragma unroll
        for (int kk = 0; kk < 8; kk++) {
            float4 a0 = *(const float4*)&As[kk][ty4];
            float4 a1 = *(const float4*)&As[kk][ty4 + 64];
            float4 b0 = *(const float4*)&Bs[kk][tx4];
            float4 b1 = *(const float4*)&Bs[kk][tx4 + 64];
            float ar[8] = {a0.x, a0.y, a0.z, a0.w, a1.x, a1.y, a1.z, a1.w};
            float br[8] = {b0.x, b0.y, b0.z, b0.w, b1.x, b1.y, b1.z, b1.w};
#pragma unroll
            for (int i = 0; i < 8; i++)
#pragma unroll
                for (int j = 0; j < 8; j++)
                    acc[i][j] = fmaf(ar[i], br[j], acc[i][j]);
        }
        __syncthreads();
    }

    float4 bias0 = *(const float4*)(bias + n0 + tx4);
    float4 bias1 = *(const float4*)(bias + n0 + tx4 + 64);
#pragma unroll
    for (int i = 0; i < 8; i++) {
        int r = (i < 4) ? (ty4 + i) : (64 + ty4 + (i - 4));
        float* orow = g_xp + (size_t)(m0 + r) * GG + n0;
        float4 o0 = make_float4(acc[i][0] + bias0.x, acc[i][1] + bias0.y,
                                acc[i][2] + bias0.z, acc[i][3] + bias0.w);
        float4 o1 = make_float4(acc[i][4] + bias1.x, acc[i][5] + bias1.y,
                                acc[i][6] + bias1.z, acc[i][7] + bias1.w);
        *(float4*)(orow + tx4)      = o0;
        *(float4*)(orow + tx4 + 64) = o1;
    }
}

// ---------------------------------------------------------------------------
// Persistent recurrence kernel.
// Smem layout (dynamic):
//   [0, 64KB)        : A double-buffer, 2 x 8-ktile chunks of h fragments
//   [64KB, 192KB)    : Wh B-fragments [ktile 64][npair 2][hl 2][lane 32] x 16B
//   [192KB, +8448)   : Ds[64][33] f32 gate results
// ---------------------------------------------------------------------------
#define AOFF 0
#define ABUF_BYTES 32768
#define WOFF 65536
#define DOFF 196608
#define DS_STRIDE 33
#define SMEM_BYTES (DOFF + 64 * DS_STRIDE * 4)

__device__ __forceinline__ void grid_barrier(unsigned target) {
    __threadfence();
    __syncthreads();
    if (threadIdx.x == 0) {
        atomicAdd(&g_bar, 1u);
        while (*((volatile unsigned*)&g_bar) < target) { }
    }
    __syncthreads();
}

__global__ __launch_bounds__(256, 1) void recurrence_kernel(const float* __restrict__ Wh) {
    extern __shared__ char smem[];
    const int tid  = threadIdx.x;
    const int blk  = blockIdx.x;
    const int warp = tid >> 5, lane = tid & 31;
    const int mw = warp & 3;        // m-tile (batches 16mw..16mw+15)
    const int np = warp >> 2;       // n-pair (gate cols 16np..16np+15)
    float* Ds = (float*)(smem + DOFF);
    const unsigned smem_u32 = (unsigned)__cvta_generic_to_shared(smem);

    // ---- one-time: stage Wh slice as B fragments (hi/lo bf16) ----
    // block owns gate cols gidx = type*1024 + 8*blk + uu  (n = type*8+uu, n in [0,32))
    for (int idx = tid; idx < 32 * 1024; idx += 256) {
        int k = idx >> 5, n = idx & 31;
        int gcol = ((n >> 3) << 10) + (blk << 3) + (n & 7);
        float w = Wh[(size_t)k * GG + gcol];
        __nv_bfloat16 hi = __float2bfloat16(w);
        __nv_bfloat16 lo = __float2bfloat16(w - __bfloat162float(hi));
        int kc = k & 15;
        int ln = ((n & 7) << 2) + ((kc & 7) >> 1);                 // lane = g*4+t
        int by = (((n >> 3) & 1) << 3) + (((kc >> 3) & 1) << 2) + ((kc & 1) << 1);
        int base = WOFF + ((((k >> 4) << 1) + (n >> 4)) << 1) * 512 + (ln << 4) + by;
        *(__nv_bfloat16*)(smem + base)       = hi;
        *(__nv_bfloat16*)(smem + base + 512) = lo;
    }
    __syncthreads();

    // per-thread cell state: batch ub, hidden units (8*blk + up) and (8*blk + up + 4)
    const int ub = tid & 63;
    const int up = tid >> 6;       // 0..3
    float creg[2] = {0.f, 0.f};

    for (int t = 0; t < TT; t++) {
        const char* hsrc = (const char*)g_hstage[t & 1];

        // prefetch chunk 0
        {
            const char* src = hsrc + tid * 16;
            unsigned dst = smem_u32 + AOFF + tid * 16;
#pragma unroll
            for (int j = 0; j < 8; j++) cpasync16(dst + j * 4096, src + j * 4096);
            asm volatile("cp.async.commit_group;");
        }

        float acc[2][4] = {{0.f,0.f,0.f,0.f},{0.f,0.f,0.f,0.f}};

        for (int c = 0; c < 8; c++) {
            if (c < 7) {
                const char* src = hsrc + (size_t)(c + 1) * ABUF_BYTES + tid * 16;
                unsigned dst = smem_u32 + AOFF + ((c + 1) & 1) * ABUF_BYTES + tid * 16;
#pragma unroll
                for (int j = 0; j < 8; j++) cpasync16(dst + j * 4096, src + j * 4096);
                asm volatile("cp.async.commit_group;");
                asm volatile("cp.async.wait_group 1;");
            } else {
                asm volatile("cp.async.wait_group 0;");
            }
            __syncthreads();

#pragma unroll
            for (int kt = 0; kt < 8; kt++) {
                unsigned ab = smem_u32 + AOFF + (c & 1) * ABUF_BYTES
                            + ((kt * 4 + mw) * 2) * 512 + (lane << 4);
                uint4 ahi = lds128(ab);
                uint4 alo = lds128(ab + 512);
                int ktg = c * 8 + kt;
                unsigned bb = smem_u32 + WOFF + ((ktg * 2 + np) * 2) * 512 + (lane << 4);
                uint4 bhi = lds128(bb);
                uint4 blo = lds128(bb + 512);
                // n-tile 0
                mma16816(acc[0], ahi, bhi.x, bhi.y);
                mma16816(acc[0], ahi, blo.x, blo.y);
                mma16816(acc[0], alo, bhi.x, bhi.y);
                // n-tile 1
                mma16816(acc[1], ahi, bhi.z, bhi.w);
                mma16816(acc[1], ahi, blo.z, blo.w);
                mma16816(acc[1], alo, bhi.z, bhi.w);
            }
            __syncthreads();
        }

        // ---- write gate results to Ds ----
        {
            int g = lane >> 2, tq = lane & 3;
            int row0 = (mw << 4) + g;
#pragma unroll
            for (int nt = 0; nt < 2; nt++) {
                int cb = (np << 4) + (nt << 3) + (tq << 1);
                Ds[row0 * DS_STRIDE + cb]            = acc[nt][0];
                Ds[row0 * DS_STRIDE + cb + 1]        = acc[nt][1];
                Ds[(row0 + 8) * DS_STRIDE + cb]      = acc[nt][2];
                Ds[(row0 + 8) * DS_STRIDE + cb + 1]  = acc[nt][3];
            }
        }
        __syncthreads();

        // ---- pointwise LSTM update for our 2 (b, unit) pairs ----
        {
            const float* xp = g_xp + ((size_t)t * BB + ub) * GG;
            char* hdst = (char*)g_hstage[(t + 1) & 1];
#pragma unroll
            for (int pi = 0; pi < 2; pi++) {
                int p = up + pi * 4;                // local unit 0..7
                int unit = (blk << 3) + p;          // global hidden unit
                float di = Ds[ub * DS_STRIDE + p];
                float df = Ds[ub * DS_STRIDE + 8 + p];
                float dg = Ds[ub * DS_STRIDE + 16 + p];
                float dz = Ds[ub * DS_STRIDE + 24 + p];
                float gi = xp[unit]          + di;
                float gf = xp[HH + unit]     + df;
                float gg = xp[2 * HH + unit] + dg;
                float go = xp[3 * HH + unit] + dz;
                float si = 1.f / (1.f + expf(-gi));
                float sf = 1.f / (1.f + expf(-gf));
                float tg = tanhf(gg);
                float so = 1.f / (1.f + expf(-go));
                float cn = fmaf(sf, creg[pi], si * tg);
                creg[pi] = cn;
                float hn = so * tanhf(cn);

                // write h into A-fragment staging (bf16 hi/lo)
                int r = ub & 15, mt = ub >> 4;
                int kc = unit & 15, ktile = unit >> 4;
                int ln  = ((r & 7) << 2) + ((kc & 7) >> 1);
                int reg = (((kc >> 3) & 1) << 1) + ((r >> 3) & 1);
                int off = (((ktile << 2) + mt) << 1) * 512 + (ln << 4)
                        + (reg << 2) + ((kc & 1) << 1);
                __nv_bfloat16 hi = __float2bfloat16(hn);
                __nv_bfloat16 lo = __float2bfloat16(hn - __bfloat162float(hi));
                *(__nv_bfloat16*)(hdst + off)       = hi;
                *(__nv_bfloat16*)(hdst + off + 512) = lo;
                if (t == TT - 1) g_h[ub * HH + unit] = hn;
            }
        }

        grid_barrier((unsigned)(NBLK * (t + 1)));
    }
}

// ---------------------------------------------------------------------------
// classifier: out[b][c] = dot(h_final[b], Wd[:,c]) + bd[c]
// ---------------------------------------------------------------------------
__global__ void classifier_kernel(const float* __restrict__ Wd,
                                  const float* __restrict__ bd,
                                  float* __restrict__ out) {
    int tid = threadIdx.x;
    if (tid >= BB * CC) return;
    int b = tid / CC, cc = tid % CC;
    const float* hr = g_h + (size_t)b * HH;
    float acc = bd[cc];
    for (int k = 0; k < HH; k++)
        acc = fmaf(hr[k], Wd[k * CC + cc], acc);
    out[tid] = acc;
}

// ---------------------------------------------------------------------------
// launch: 4 graph nodes total
// ---------------------------------------------------------------------------
extern "C" void kernel_launch(void* const* d_in, const int* in_sizes, int n_in,
                              void* d_out, int out_size) {
    const int*   tokens = (const int*)d_in[0];
    const float* emb    = (const float*)d_in[1];
    const float* Wi     = (const float*)d_in[2];
    const float* Wh     = (const float*)d_in[3];
    const float* bias   = (const float*)d_in[4];
    const float* Wd     = (const float*)d_in[5];
    const float* bd     = (const float*)d_in[6];
    float* out = (float*)d_out;

    cudaFuncSetAttribute(recurrence_kernel,
                         cudaFuncAttributeMaxDynamicSharedMemorySize, SMEM_BYTES);

    init_kernel<<<64, 256>>>();

    dim3 xg(TT * BB / 128, GG / 128);   // (256, 32)
    xproj_kernel<<<xg, 256>>>(tokens, emb, Wi, bias);

    recurrence_kernel<<<NBLK, 256, SMEM_BYTES>>>(Wh);

    classifier_kernel<<<1, 256>>>(Wd, bd, out);
}